// round 6
// baseline (speedup 1.0000x reference)
#include <cuda_runtime.h>
#include <math.h>
#include <float.h>

#define H     2048
#define NK    4
#define NIT   9
#define MULTC 0.001f
#define MAXC  12
#define MAXP  66
#define MAXB  528   // 66 pairs * 4 k * 2 binary
#define NWRD  ((MAXB + 31) / 32)

// ---------------- device state (no allocations allowed) ----------------
// d_T[lr][slot][k][d]: cached projections. slot 0=x,1=h,2=zero,3+g = G_g
__device__ float d_T[2][12][NK][H];
__device__ float d_S[H];                  // sum over bases of MULT*(sig+tanh)
__device__ float d_stvec[MAXB][H];        // per-base MULT*(sig+tanh) vector
__device__ float d_stats[MAXB][5];        // rdot, sigdot, tanhdot, mdot, absmax
__device__ int   d_pairs[MAXP][2];
__device__ int   d_cand[MAXC];            // candidate index -> slot
__device__ int   d_comp[NIT];             // comp_src (G indices)
__device__ int   d_npairs, d_nc, d_lc;
__device__ int   d_nbcur;                 // base count for CURRENT iteration
__device__ float d_p, d_ns, d_wsum;

// ---------------- init ----------------------------------------------------
__global__ void init_kernel(const float* __restrict__ w) {
    int t = threadIdx.x;
    for (int idx = t; idx < 2 * NK * H; idx += blockDim.x) {
        int lr = idx / (NK * H);
        int rem = idx % (NK * H);
        d_T[lr][2][rem / H][rem % H] = 0.f;
    }
    __shared__ float red[256];
    float acc = 0.f;
    for (int d = t; d < H; d += 256) acc += w[d];
    red[t] = acc;
    __syncthreads();
    for (int s = 128; s > 0; s >>= 1) {
        if (t < s) red[t] += red[t + s];
        __syncthreads();
    }
    if (t == 0) {
        d_wsum = red[0];
        d_pairs[0][0] = 0; d_pairs[0][1] = 1;
        d_pairs[1][0] = 0; d_pairs[1][1] = 2;
        d_pairs[2][0] = 1; d_pairs[2][1] = 2;
        d_npairs = 3; d_nc = 3; d_lc = 0;
        d_cand[0] = 0; d_cand[1] = 1; d_cand[2] = 2;
    }
}

// ---------------- GEMV: 256 blocks/matrix-set, 256 threads ----------------
// Tiling: 8 matrices x 32 chunks of 64 columns. Thread = one float4 column
// group (cg 0..15) x one 128-row h-slice (sl 0..15). 16-slice smem reduce
// in fixed order -> deterministic.
// useS==0: two input vectors v0,v1 -> slots slot0, slot0+1 (grid 512)
// useS==1: vector = d_p*(d_S+d_ns) -> slot slot0; m==0 blocks also write
//          Gs[r] chunk to out (grid 256)
__global__ void gemv_kernel(const float* __restrict__ v0,
                            const float* __restrict__ v1, int useS,
                            const float* __restrict__ L,
                            const float* __restrict__ R,
                            int slot0, float* __restrict__ out, int r) {
    __shared__ float v[H];
    __shared__ float4 red4[16][16];
    const int per = 8 * 32;           // 256 blocks per vector
    int vi  = blockIdx.x / per;
    int rem = blockIdx.x % per;
    int m   = rem >> 5, db = rem & 31;
    int t = threadIdx.x;              // 256 threads

    if (useS) {
        float p = d_p, ns = d_ns;
#pragma unroll
        for (int ii = 0; ii < 2; ii++) {
            float4 s4 = ((const float4*)d_S)[t + ii * 256];
            float4 g4;
            g4.x = p * (s4.x + ns); g4.y = p * (s4.y + ns);
            g4.z = p * (s4.z + ns); g4.w = p * (s4.w + ns);
            ((float4*)v)[t + ii * 256] = g4;
        }
    } else {
        const float* vec = (vi == 0) ? v0 : v1;
#pragma unroll
        for (int ii = 0; ii < 2; ii++)
            ((float4*)v)[t + ii * 256] = ((const float4*)vec)[t + ii * 256];
    }
    __syncthreads();

    if (useS && m == 0 && t < 64)
        out[H + r * H + db * 64 + t] = v[db * 64 + t];   // Gs[r] chunk

    int lr = m >> 2, k = m & 3;
    int cg = t & 15;                  // float4-column group within chunk
    int sl = t >> 4;                  // h-slice 0..15 (128 rows each)
    int d4 = db * 16 + cg;            // global float4 column 0..511
    const float4* M4 = (const float4*)((lr ? R : L) + (size_t)k * H * H);
    int h0 = sl * 128;
    float4 acc = make_float4(0.f, 0.f, 0.f, 0.f);
#pragma unroll 16
    for (int h = 0; h < 128; h++) {
        float4 mv = M4[(size_t)(h0 + h) * (H / 4) + d4];
        float vh = v[h0 + h];
        acc.x = fmaf(vh, mv.x, acc.x);
        acc.y = fmaf(vh, mv.y, acc.y);
        acc.z = fmaf(vh, mv.z, acc.z);
        acc.w = fmaf(vh, mv.w, acc.w);
    }
    red4[sl][cg] = acc;
    __syncthreads();
    if (sl == 0) {
        float4 s = red4[0][cg];
#pragma unroll
        for (int u = 1; u < 16; u++) {
            float4 rr = red4[u][cg];
            s.x += rr.x; s.y += rr.y; s.z += rr.z; s.w += rr.w;
        }
        ((float4*)d_T[lr][slot0 + vi][k])[d4] = s;
    }
}

// ---------------- per-base stats + sig/tanh vector -------------------------
__global__ void stats_kernel(const float* __restrict__ b,
                             const float* __restrict__ w) {
    int np = d_npairs;
    if (blockIdx.x == 0 && threadIdx.x == 0) d_nbcur = np * 8;
    int pid = blockIdx.x >> 3;
    if (pid >= np) return;
    int kb = blockIdx.x & 7;
    int k = kb >> 1, bf = kb & 1;     // bf: 0=mul, 1=add
    int i = d_pairs[pid][0], j = d_pairs[pid][1];
    const float4* CL = (const float4*)d_T[0][d_cand[i]][k];
    const float4* CR = (const float4*)d_T[1][d_cand[j]][k];
    const float4* BK = (const float4*)(b + k * H);
    const float4* W4 = (const float4*)w;
    float4* SV = (float4*)d_stvec[pid * 8 + kb];
    int tid = threadIdx.x;

    float rdot = 0.f, sdot = 0.f, tdot = 0.f, mdot = 0.f, amax = 0.f;
#pragma unroll
    for (int ii = 0; ii < 2; ii++) {
        int idx = tid + ii * 256;     // 0..511 float4 indices
        float4 a4 = CL[idx], c4 = CR[idx], b4 = BK[idx], w4 = W4[idx];
        float res[4], wd[4];
        if (bf) {
            res[0] = a4.x + c4.x + b4.x; res[1] = a4.y + c4.y + b4.y;
            res[2] = a4.z + c4.z + b4.z; res[3] = a4.w + c4.w + b4.w;
        } else {
            res[0] = fmaf(a4.x, c4.x, b4.x); res[1] = fmaf(a4.y, c4.y, b4.y);
            res[2] = fmaf(a4.z, c4.z, b4.z); res[3] = fmaf(a4.w, c4.w, b4.w);
        }
        wd[0] = w4.x; wd[1] = w4.y; wd[2] = w4.z; wd[3] = w4.w;
        float st4[4];
#pragma unroll
        for (int u = 0; u < 4; u++) {
            float rr = res[u];
            float sg = 1.f / (1.f + __expf(-rr));
            float th = tanhf(rr);
            rdot = fmaf(rr, wd[u], rdot);
            sdot = fmaf(sg, wd[u], sdot);
            tdot = fmaf(th, wd[u], tdot);
            mdot = fmaf(1.f - rr, wd[u], mdot);
            amax = fmaxf(amax, fabsf(rr));
            st4[u] = MULTC * (sg + th);
        }
        float4 o4; o4.x = st4[0]; o4.y = st4[1]; o4.z = st4[2]; o4.w = st4[3];
        SV[idx] = o4;
    }
    __shared__ float sh[5][256];
    sh[0][tid] = rdot; sh[1][tid] = sdot; sh[2][tid] = tdot;
    sh[3][tid] = mdot; sh[4][tid] = amax;
    __syncthreads();
    for (int s = 128; s > 0; s >>= 1) {
        if (tid < s) {
            sh[0][tid] += sh[0][tid + s];
            sh[1][tid] += sh[1][tid + s];
            sh[2][tid] += sh[2][tid + s];
            sh[3][tid] += sh[3][tid + s];
            sh[4][tid] = fmaxf(sh[4][tid], sh[4][tid + s]);
        }
        __syncthreads();
    }
    if (tid == 0) {
        int base = pid * 8 + kb;
        d_stats[base][0] = sh[0][0];
        d_stats[base][1] = sh[1][0];
        d_stats[base][2] = sh[2][0];
        d_stats[base][3] = sh[3][0];
        d_stats[base][4] = sh[4][0];
    }
}

// prefix of entry index for base bb: 2*bb + 2*(#small bases before bb)
__device__ __forceinline__ int prefixE(const unsigned* fl, int bb) {
    int pc = 0, wI = bb >> 5;
    for (int k = 0; k < wI; k++) pc += __popc(fl[k]);
    pc += __popc(fl[wI] & ((1u << (bb & 31)) - 1u));
    return 2 * bb + 2 * pc;
}

// ---------------- fused: block 0 = decide, blocks 1..16 = sumS ------------
__global__ void fused_kernel(float* __restrict__ out, int r) {
    if (blockIdx.x > 0) {
        // sumS: deterministic 2-way row split, fixed combine order
        int bi = blockIdx.x - 1;          // 0..15
        int t = threadIdx.x;
        int d = bi * 128 + (t & 127);
        int half = t >> 7;
        int nb = d_nbcur;
        float acc = 0.f;
        for (int bb = half; bb < nb; bb += 2) acc += d_stvec[bb][d];
        __shared__ float sh[256];
        sh[t] = acc;
        __syncthreads();
        if (half == 0) d_S[d] = sh[t] + sh[t + 128];
        return;
    }

    // -------- decide (block 0, 256 threads) --------
    __shared__ float st[MAXB * 5];
    __shared__ unsigned sflag[NWRD];
    __shared__ unsigned long long wkey[8];
    __shared__ float wsd[8], wse[8], wmx[8];
    __shared__ int wcl[8], wns[8];
    __shared__ float g_smax, g_sq, g_sec;
    __shared__ int g_rank;
    __shared__ unsigned long long g_key;

    int t = threadIdx.x;
    int lane = t & 31, wrp = t >> 5;
    int nb = d_npairs * 8;
    int nc = d_nc;
    int q = nc - 2;

    for (int i = t; i < nb * 5; i += 256)
        st[i] = ((const float*)d_stats)[i];
    __syncthreads();

    int nw = (nb + 31) >> 5;
    for (int wI = t; wI < nw; wI += 256) {
        unsigned wrd = 0;
        int lim = min(32, nb - wI * 32);
        for (int jj = 0; jj < lim; jj++)
            if (st[(wI * 32 + jj) * 5 + 4] < 1.0f) wrd |= 1u << jj;
        sflag[wI] = wrd;
    }
    __syncthreads();

    float s1v = MULTC * st[0 * 5 + 2];
    float s0v = MULTC * st[0 * 5 + 1];

    // pass 1
    unsigned long long bestkey = 0ull;
    float sdsum = 0.f, mx = -FLT_MAX;
    int cl = 0, ns = 0;
    for (int bb = t; bb < nb; bb += 256) {
        float rdot = st[bb * 5 + 0], sdot = st[bb * 5 + 1];
        float tdot = st[bb * 5 + 2], mdot = st[bb * 5 + 3];
        bool small = st[bb * 5 + 4] < 1.0f;
        sdsum += sdot + tdot;
        float s[4] = {MULTC * sdot, MULTC * tdot, mdot, rdot};
        int na = small ? 4 : 2;
        if (small) ns++;
        int e0 = prefixE(sflag, bb);
        for (int a = 0; a < na; a++) {
            float v = s[a];
            int idx = e0 + a;
            unsigned sb = __float_as_uint(v);
            sb = (sb & 0x80000000u) ? ~sb : (sb | 0x80000000u);
            unsigned long long key =
                ((unsigned long long)sb << 24) |
                ((unsigned long long)(4095 - idx) << 12) |
                (unsigned long long)bb;
            if (key > bestkey) bestkey = key;
            mx = fmaxf(mx, v);
            if (v < s1v) cl++;
            if (idx == q) g_sq = v;          // exactly one writer
        }
    }
    for (int o = 16; o; o >>= 1) {
        unsigned long long ok = __shfl_xor_sync(0xffffffffu, bestkey, o);
        if (ok > bestkey) bestkey = ok;
        sdsum += __shfl_xor_sync(0xffffffffu, sdsum, o);
        mx = fmaxf(mx, __shfl_xor_sync(0xffffffffu, mx, o));
        cl += __shfl_xor_sync(0xffffffffu, cl, o);
        ns += __shfl_xor_sync(0xffffffffu, ns, o);
    }
    if (lane == 0) {
        wkey[wrp] = bestkey; wsd[wrp] = sdsum; wmx[wrp] = mx;
        wcl[wrp] = cl; wns[wrp] = ns;
    }
    __syncthreads();
    if (t == 0) {
        unsigned long long BK = 0ull;
        float SD = 0.f, MXv = -FLT_MAX;
        int CL = 0, NS = 0;
        for (int u = 0; u < 8; u++) {
            if (wkey[u] > BK) BK = wkey[u];
            SD += wsd[u]; MXv = fmaxf(MXv, wmx[u]);
            CL += wcl[u]; NS += wns[u];
        }
        g_key = BK; g_smax = MXv;
        g_rank = CL + ((s0v == s1v) ? 1 : 0);
        wsd[0] = SD; wns[0] = NS;             // reuse for final section
    }
    __syncthreads();

    // pass 2: softmax denom + rank selection
    float MX = g_smax;
    int rank = g_rank;
    float se = 0.f;
    for (int bb = t; bb < nb; bb += 256) {
        float rdot = st[bb * 5 + 0], sdot = st[bb * 5 + 1];
        float tdot = st[bb * 5 + 2], mdot = st[bb * 5 + 3];
        bool small = st[bb * 5 + 4] < 1.0f;
        float s[4] = {MULTC * sdot, MULTC * tdot, mdot, rdot};
        int na = small ? 4 : 2;
        int e0 = prefixE(sflag, bb);
        for (int a = 0; a < na; a++) {
            se += __expf(s[a] - MX);
            if (e0 + a == rank) g_sec = s[a];
        }
    }
    for (int o = 16; o; o >>= 1)
        se += __shfl_xor_sync(0xffffffffu, se, o);
    if (lane == 0) wse[wrp] = se;
    __syncthreads();

    if (t == 0) {
        float SE = 0.f;
        for (int u = 0; u < 8; u++) SE += wse[u];
        float p = __expf(g_sq - MX) / SE;
        float NS = (float)wns[0];
        d_p = p;
        d_ns = NS;
        out[H + NIT * H + r] = p * (MULTC * wsd[0] + NS * d_wsum);  // Gs@w
        out[H + NIT * H + NIT + r] = g_sec;                         // second@w

        // comp_src update from argmax entry (base carried in key)
        int bb = (int)(g_key & 0xfffull);
        int pid = bb >> 3;
        int pi = d_pairs[pid][0], pj = d_pairs[pid][1];
        int lc = d_lc;
        if (pi > 2 && pj > 2) {
            d_comp[pi - 3] = r;
            for (int u = pj - 3; u < lc - 1; u++) d_comp[u] = d_comp[u + 1];
            lc--;
        } else if (pj > 2) {
            d_comp[pj - 3] = r;
        } else {
            d_comp[lc] = r; lc++;
        }
        d_lc = lc;
        int ncn = 3 + lc;
        d_nc = ncn;
        for (int u = 0; u < lc; u++) d_cand[3 + u] = 3 + d_comp[u];

        int nri = NIT - (r + 1);
        int np = 0;
        for (int ii = 0; ii < ncn - 1; ii++)
            for (int jj = ii + 1; jj < ncn; jj++) {
                bool flag;
                if (nri == lc - 1)      flag = (ii >= 3);
                else if (nri == lc)     flag = (jj >= 3);
                else                    flag = (nri > lc);
                if (flag) { d_pairs[np][0] = ii; d_pairs[np][1] = jj; np++; }
            }
        d_npairs = np;
    }
}

// ---------------- final G for r==8 (no gemv follows) ----------------------
__global__ void finalG_kernel(float* __restrict__ out) {
    int d = blockIdx.x * 128 + threadIdx.x;   // grid 16 x 128
    float g = d_p * (d_S[d] + d_ns);
    out[d] = g;                     // h_next
    out[H + (NIT - 1) * H + d] = g; // Gs[8]
}

// ---------------- launch --------------------------------------------------
extern "C" void kernel_launch(void* const* d_in, const int* in_sizes, int n_in,
                              void* d_out, int out_size) {
    const float* x = (const float*)d_in[0];
    const float* h = (const float*)d_in[1];
    const float* L = (const float*)d_in[2];
    const float* R = (const float*)d_in[3];
    const float* b = (const float*)d_in[4];
    const float* w = (const float*)d_in[5];
    float* out = (float*)d_out;

    init_kernel<<<1, 256>>>(w);
    gemv_kernel<<<512, 256>>>(x, h, 0, L, R, 0, nullptr, 0);

    for (int r = 0; r < NIT; r++) {
        stats_kernel<<<MAXB, 256>>>(b, w);
        fused_kernel<<<17, 256>>>(out, r);
        if (r < NIT - 1)
            gemv_kernel<<<256, 256>>>(nullptr, nullptr, 1, L, R, 3 + r, out, r);
        else
            finalG_kernel<<<16, 128>>>(out);
    }
}

// round 8
// speedup vs baseline: 1.8785x; 1.8785x over previous
#include <cuda_runtime.h>
#include <cuda_fp16.h>
#include <math.h>
#include <float.h>

#define H     2048
#define NK    4
#define NIT   9
#define MULTC 0.001f
#define MAXC  12
#define MAXP  66
#define MAXB  528   // 66 pairs * 4 k * 2 binary
#define NWRD  ((MAXB + 31) / 32)

// ---------------- device state (no allocations allowed) ----------------
// d_T[lr][slot][k][d]: cached projections. slot 0=x,1=h,2=zero,3+g = G_g
__device__ float d_T[2][12][NK][H];
__device__ float d_S[H];                  // sum over bases of MULT*(sig+tanh)
__device__ float d_stvec[MAXB][H];        // per-base MULT*(sig+tanh) vector
__device__ float d_stats[MAXB][5];        // rdot, sigdot, tanhdot, mdot, absmax
__device__ __half d_MB[8ull * H * H];     // fp16 L(0..3)+R(4..7), 64 MB
__device__ int   d_pairs[MAXP][2];
__device__ int   d_cand[MAXC];            // candidate index -> slot
__device__ int   d_comp[NIT];             // comp_src (G indices)
__device__ int   d_npairs, d_nc, d_lc;
__device__ int   d_nbcur;                 // base count for CURRENT iteration
__device__ float d_p, d_ns, d_wsum;

// ---------------- init ----------------------------------------------------
__global__ void init_kernel(const float* __restrict__ w) {
    int t = threadIdx.x;
    for (int idx = t; idx < 2 * NK * H; idx += blockDim.x) {
        int lr = idx / (NK * H);
        int rem = idx % (NK * H);
        d_T[lr][2][rem / H][rem % H] = 0.f;
    }
    __shared__ float red[256];
    float acc = 0.f;
    for (int d = t; d < H; d += 256) acc += w[d];
    red[t] = acc;
    __syncthreads();
    for (int s = 128; s > 0; s >>= 1) {
        if (t < s) red[t] += red[t + s];
        __syncthreads();
    }
    if (t == 0) {
        d_wsum = red[0];
        d_pairs[0][0] = 0; d_pairs[0][1] = 1;
        d_pairs[1][0] = 0; d_pairs[1][1] = 2;
        d_pairs[2][0] = 1; d_pairs[2][1] = 2;
        d_npairs = 3; d_nc = 3; d_lc = 0;
        d_cand[0] = 0; d_cand[1] = 1; d_cand[2] = 2;
    }
}

// ---------------- convert L,R (fp32) -> d_MB (fp16) ------------------------
__global__ void convert_kernel(const float* __restrict__ L,
                               const float* __restrict__ R) {
    const size_t total4 = 8ull * H * H / 4;   // float4 count
    const size_t half4  = 4ull * H * H / 4;
    size_t stride = (size_t)gridDim.x * blockDim.x;
    for (size_t i = (size_t)blockIdx.x * blockDim.x + threadIdx.x;
         i < total4; i += stride) {
        const float4 f = (i < half4) ? ((const float4*)L)[i]
                                     : ((const float4*)R)[i - half4];
        __half2 a, b;
        a.x = __float2half_rn(f.x); a.y = __float2half_rn(f.y);
        b.x = __float2half_rn(f.z); b.y = __float2half_rn(f.w);
        ((__half2*)d_MB)[i * 2]     = a;
        ((__half2*)d_MB)[i * 2 + 1] = b;
    }
}

// ---------------- dummy (ncu slot alignment) -------------------------------
__global__ void dummy_kernel() {}

// ---------------- GEMV (fp16 matrices, uint4 loads) ------------------------
// Tiling: 8 matrices x 16 chunks of 128 columns; 512 threads.
// Thread = uint4 column-group cg (16 per chunk, 8 fp16 cols each) x 64-row
// slice sl (32 slices). Fixed-order smem reduce -> deterministic.
// useS==0: two vectors v0,v1 -> slots slot0,slot0+1 (grid 256)
// useS==1: vector = d_p*(d_S+d_ns) -> slot slot0; m==0 writes Gs[r] (grid 128)
__global__ void gemv_kernel(const float* __restrict__ v0,
                            const float* __restrict__ v1, int useS,
                            int slot0, float* __restrict__ out, int r) {
    __shared__ float v[H];
    __shared__ float red[32][16][8];
    const int per = 128;              // 8 matrices * 16 chunks
    int vi  = blockIdx.x / per;
    int rem = blockIdx.x % per;
    int m   = rem >> 4, db = rem & 15;
    int t = threadIdx.x;              // 512

    if (useS) {
        float p = d_p, ns = d_ns;
        float4 s4 = ((const float4*)d_S)[t];
        float4 g4;
        g4.x = p * (s4.x + ns); g4.y = p * (s4.y + ns);
        g4.z = p * (s4.z + ns); g4.w = p * (s4.w + ns);
        ((float4*)v)[t] = g4;
    } else {
        const float* vec = (vi == 0) ? v0 : v1;
        ((float4*)v)[t] = ((const float4*)vec)[t];
    }
    __syncthreads();

    if (useS && m == 0 && t < 128)
        out[H + r * H + db * 128 + t] = v[db * 128 + t];   // Gs[r] chunk

    int cg = t & 15;                  // uint4 col group within chunk
    int sl = t >> 4;                  // 64-row slice 0..31
    int d8 = db * 16 + cg;            // global uint4 column 0..255
    const uint4* M4 = (const uint4*)(d_MB + (size_t)m * H * H);
    int h0 = sl * 64;
    float a0=0.f,a1=0.f,a2=0.f,a3=0.f,a4=0.f,a5=0.f,a6=0.f,a7=0.f;
#pragma unroll 8
    for (int h = 0; h < 64; h++) {
        uint4 mv = M4[(size_t)(h0 + h) * (H / 8) + d8];
        float vh = v[h0 + h];
        float2 f0 = __half22float2(*(__half2*)&mv.x);
        float2 f1 = __half22float2(*(__half2*)&mv.y);
        float2 f2 = __half22float2(*(__half2*)&mv.z);
        float2 f3 = __half22float2(*(__half2*)&mv.w);
        a0 = fmaf(vh, f0.x, a0); a1 = fmaf(vh, f0.y, a1);
        a2 = fmaf(vh, f1.x, a2); a3 = fmaf(vh, f1.y, a3);
        a4 = fmaf(vh, f2.x, a4); a5 = fmaf(vh, f2.y, a5);
        a6 = fmaf(vh, f3.x, a6); a7 = fmaf(vh, f3.y, a7);
    }
    red[sl][cg][0]=a0; red[sl][cg][1]=a1; red[sl][cg][2]=a2; red[sl][cg][3]=a3;
    red[sl][cg][4]=a4; red[sl][cg][5]=a5; red[sl][cg][6]=a6; red[sl][cg][7]=a7;
    __syncthreads();
    if (sl == 0) {
        float s[8];
#pragma unroll
        for (int u = 0; u < 8; u++) s[u] = red[0][cg][u];
#pragma unroll
        for (int z = 1; z < 32; z++)
#pragma unroll
            for (int u = 0; u < 8; u++) s[u] += red[z][cg][u];
        int lr = m >> 2, k = m & 3;
        float* Td = d_T[lr][slot0 + vi][k];
        float4 o0, o1;
        o0.x=s[0]; o0.y=s[1]; o0.z=s[2]; o0.w=s[3];
        o1.x=s[4]; o1.y=s[5]; o1.z=s[6]; o1.w=s[7];
        ((float4*)Td)[d8 * 2]     = o0;
        ((float4*)Td)[d8 * 2 + 1] = o1;
    }
}

// ---------------- per-base stats + sig/tanh vector -------------------------
__global__ void stats_kernel(const float* __restrict__ b,
                             const float* __restrict__ w) {
    int np = d_npairs;
    if (blockIdx.x == 0 && threadIdx.x == 0) d_nbcur = np * 8;
    int pid = blockIdx.x >> 3;
    if (pid >= np) return;
    int kb = blockIdx.x & 7;
    int k = kb >> 1, bf = kb & 1;     // bf: 0=mul, 1=add
    int i = d_pairs[pid][0], j = d_pairs[pid][1];
    const float4* CL = (const float4*)d_T[0][d_cand[i]][k];
    const float4* CR = (const float4*)d_T[1][d_cand[j]][k];
    const float4* BK = (const float4*)(b + k * H);
    const float4* W4 = (const float4*)w;
    float4* SV = (float4*)d_stvec[pid * 8 + kb];
    int tid = threadIdx.x;

    float rdot = 0.f, sdot = 0.f, tdot = 0.f, mdot = 0.f, amax = 0.f;
#pragma unroll
    for (int ii = 0; ii < 2; ii++) {
        int idx = tid + ii * 256;     // 0..511 float4 indices
        float4 a4 = CL[idx], c4 = CR[idx], b4 = BK[idx], w4 = W4[idx];
        float res[4], wd[4];
        if (bf) {
            res[0] = a4.x + c4.x + b4.x; res[1] = a4.y + c4.y + b4.y;
            res[2] = a4.z + c4.z + b4.z; res[3] = a4.w + c4.w + b4.w;
        } else {
            res[0] = fmaf(a4.x, c4.x, b4.x); res[1] = fmaf(a4.y, c4.y, b4.y);
            res[2] = fmaf(a4.z, c4.z, b4.z); res[3] = fmaf(a4.w, c4.w, b4.w);
        }
        wd[0] = w4.x; wd[1] = w4.y; wd[2] = w4.z; wd[3] = w4.w;
        float st4[4];
#pragma unroll
        for (int u = 0; u < 4; u++) {
            float rr = res[u];
            float sg = 1.f / (1.f + __expf(-rr));
            float th = tanhf(rr);
            rdot = fmaf(rr, wd[u], rdot);
            sdot = fmaf(sg, wd[u], sdot);
            tdot = fmaf(th, wd[u], tdot);
            mdot = fmaf(1.f - rr, wd[u], mdot);
            amax = fmaxf(amax, fabsf(rr));
            st4[u] = MULTC * (sg + th);
        }
        float4 o4; o4.x = st4[0]; o4.y = st4[1]; o4.z = st4[2]; o4.w = st4[3];
        SV[idx] = o4;
    }
    __shared__ float sh[5][256];
    sh[0][tid] = rdot; sh[1][tid] = sdot; sh[2][tid] = tdot;
    sh[3][tid] = mdot; sh[4][tid] = amax;
    __syncthreads();
    for (int s = 128; s > 0; s >>= 1) {
        if (tid < s) {
            sh[0][tid] += sh[0][tid + s];
            sh[1][tid] += sh[1][tid + s];
            sh[2][tid] += sh[2][tid + s];
            sh[3][tid] += sh[3][tid + s];
            sh[4][tid] = fmaxf(sh[4][tid], sh[4][tid + s]);
        }
        __syncthreads();
    }
    if (tid == 0) {
        int base = pid * 8 + kb;
        d_stats[base][0] = sh[0][0];
        d_stats[base][1] = sh[1][0];
        d_stats[base][2] = sh[2][0];
        d_stats[base][3] = sh[3][0];
        d_stats[base][4] = sh[4][0];
    }
}

// prefix of entry index for base bb: 2*bb + 2*(#small bases before bb)
__device__ __forceinline__ int prefixE(const unsigned* fl, int bb) {
    int pc = 0, wI = bb >> 5;
    for (int k = 0; k < wI; k++) pc += __popc(fl[k]);
    pc += __popc(fl[wI] & ((1u << (bb & 31)) - 1u));
    return 2 * bb + 2 * pc;
}

// ---------------- fused: block 0 = decide, blocks 1..16 = sumS ------------
__global__ void fused_kernel(float* __restrict__ out, int r) {
    if (blockIdx.x > 0) {
        int bi = blockIdx.x - 1;          // 0..15
        int t = threadIdx.x;
        int d = bi * 128 + (t & 127);
        int half = t >> 7;
        int nb = d_nbcur;
        float acc = 0.f;
        for (int bb = half; bb < nb; bb += 2) acc += d_stvec[bb][d];
        __shared__ float sh[256];
        sh[t] = acc;
        __syncthreads();
        if (half == 0) d_S[d] = sh[t] + sh[t + 128];
        return;
    }

    // -------- decide (block 0, 256 threads) --------
    __shared__ float st[MAXB * 5];
    __shared__ unsigned sflag[NWRD];
    __shared__ unsigned long long wkey[8];
    __shared__ float wsd[8], wse[8], wmx[8];
    __shared__ int wcl[8], wns[8];
    __shared__ float g_smax, g_sq, g_sec;
    __shared__ int g_rank;
    __shared__ unsigned long long g_key;

    int t = threadIdx.x;
    int lane = t & 31, wrp = t >> 5;
    int nb = d_npairs * 8;
    int nc = d_nc;
    int q = nc - 2;

    for (int i = t; i < nb * 5; i += 256)
        st[i] = ((const float*)d_stats)[i];
    __syncthreads();

    int nw = (nb + 31) >> 5;
    for (int wI = t; wI < nw; wI += 256) {
        unsigned wrd = 0;
        int lim = min(32, nb - wI * 32);
        for (int jj = 0; jj < lim; jj++)
            if (st[(wI * 32 + jj) * 5 + 4] < 1.0f) wrd |= 1u << jj;
        sflag[wI] = wrd;
    }
    __syncthreads();

    float s1v = MULTC * st[0 * 5 + 2];
    float s0v = MULTC * st[0 * 5 + 1];

    // pass 1
    unsigned long long bestkey = 0ull;
    float sdsum = 0.f, mx = -FLT_MAX;
    int cl = 0, ns = 0;
    for (int bb = t; bb < nb; bb += 256) {
        float rdot = st[bb * 5 + 0], sdot = st[bb * 5 + 1];
        float tdot = st[bb * 5 + 2], mdot = st[bb * 5 + 3];
        bool small = st[bb * 5 + 4] < 1.0f;
        sdsum += sdot + tdot;
        float s[4] = {MULTC * sdot, MULTC * tdot, mdot, rdot};
        int na = small ? 4 : 2;
        if (small) ns++;
        int e0 = prefixE(sflag, bb);
        for (int a = 0; a < na; a++) {
            float v = s[a];
            int idx = e0 + a;
            unsigned sb = __float_as_uint(v);
            sb = (sb & 0x80000000u) ? ~sb : (sb | 0x80000000u);
            unsigned long long key =
                ((unsigned long long)sb << 24) |
                ((unsigned long long)(4095 - idx) << 12) |
                (unsigned long long)bb;
            if (key > bestkey) bestkey = key;
            mx = fmaxf(mx, v);
            if (v < s1v) cl++;
            if (idx == q) g_sq = v;          // exactly one writer
        }
    }
    for (int o = 16; o; o >>= 1) {
        unsigned long long ok = __shfl_xor_sync(0xffffffffu, bestkey, o);
        if (ok > bestkey) bestkey = ok;
        sdsum += __shfl_xor_sync(0xffffffffu, sdsum, o);
        mx = fmaxf(mx, __shfl_xor_sync(0xffffffffu, mx, o));
        cl += __shfl_xor_sync(0xffffffffu, cl, o);
        ns += __shfl_xor_sync(0xffffffffu, ns, o);
    }
    if (lane == 0) {
        wkey[wrp] = bestkey; wsd[wrp] = sdsum; wmx[wrp] = mx;
        wcl[wrp] = cl; wns[wrp] = ns;
    }
    __syncthreads();
    if (t == 0) {
        unsigned long long BK = 0ull;
        float SD = 0.f, MXv = -FLT_MAX;
        int CL = 0, NS = 0;
        for (int u = 0; u < 8; u++) {
            if (wkey[u] > BK) BK = wkey[u];
            SD += wsd[u]; MXv = fmaxf(MXv, wmx[u]);
            CL += wcl[u]; NS += wns[u];
        }
        g_key = BK; g_smax = MXv;
        g_rank = CL + ((s0v == s1v) ? 1 : 0);
        wsd[0] = SD; wns[0] = NS;
    }
    __syncthreads();

    // pass 2: softmax denom + rank selection
    float MX = g_smax;
    int rank = g_rank;
    float se = 0.f;
    for (int bb = t; bb < nb; bb += 256) {
        float rdot = st[bb * 5 + 0], sdot = st[bb * 5 + 1];
        float tdot = st[bb * 5 + 2], mdot = st[bb * 5 + 3];
        bool small = st[bb * 5 + 4] < 1.0f;
        float s[4] = {MULTC * sdot, MULTC * tdot, mdot, rdot};
        int na = small ? 4 : 2;
        int e0 = prefixE(sflag, bb);
        for (int a = 0; a < na; a++) {
            se += __expf(s[a] - MX);
            if (e0 + a == rank) g_sec = s[a];
        }
    }
    for (int o = 16; o; o >>= 1)
        se += __shfl_xor_sync(0xffffffffu, se, o);
    if (lane == 0) wse[wrp] = se;
    __syncthreads();

    if (t == 0) {
        float SE = 0.f;
        for (int u = 0; u < 8; u++) SE += wse[u];
        float p = __expf(g_sq - MX) / SE;
        float NS = (float)wns[0];
        d_p = p;
        d_ns = NS;
        out[H + NIT * H + r] = p * (MULTC * wsd[0] + NS * d_wsum);  // Gs@w
        out[H + NIT * H + NIT + r] = g_sec;                         // second@w

        int bb = (int)(g_key & 0xfffull);
        int pid = bb >> 3;
        int pi = d_pairs[pid][0], pj = d_pairs[pid][1];
        int lc = d_lc;
        if (pi > 2 && pj > 2) {
            d_comp[pi - 3] = r;
            for (int u = pj - 3; u < lc - 1; u++) d_comp[u] = d_comp[u + 1];
            lc--;
        } else if (pj > 2) {
            d_comp[pj - 3] = r;
        } else {
            d_comp[lc] = r; lc++;
        }
        d_lc = lc;
        int ncn = 3 + lc;
        d_nc = ncn;
        for (int u = 0; u < lc; u++) d_cand[3 + u] = 3 + d_comp[u];

        int nri = NIT - (r + 1);
        int np = 0;
        for (int ii = 0; ii < ncn - 1; ii++)
            for (int jj = ii + 1; jj < ncn; jj++) {
                bool flag;
                if (nri == lc - 1)      flag = (ii >= 3);
                else if (nri == lc)     flag = (jj >= 3);
                else                    flag = (nri > lc);
                if (flag) { d_pairs[np][0] = ii; d_pairs[np][1] = jj; np++; }
            }
        d_npairs = np;
    }
}

// ---------------- final G for r==8 -----------------------------------------
__global__ void finalG_kernel(float* __restrict__ out) {
    int d = blockIdx.x * 128 + threadIdx.x;   // grid 16 x 128
    float g = d_p * (d_S[d] + d_ns);
    out[d] = g;                     // h_next
    out[H + (NIT - 1) * H + d] = g; // Gs[8]
}

// ---------------- launch ---------------------------------------------------
extern "C" void kernel_launch(void* const* d_in, const int* in_sizes, int n_in,
                              void* d_out, int out_size) {
    const float* x = (const float*)d_in[0];
    const float* h = (const float*)d_in[1];
    const float* L = (const float*)d_in[2];
    const float* R = (const float*)d_in[3];
    const float* b = (const float*)d_in[4];
    const float* w = (const float*)d_in[5];
    float* out = (float*)d_out;

    init_kernel<<<1, 256>>>(w);
    convert_kernel<<<4096, 256>>>(L, R);
    dummy_kernel<<<1, 1>>>();                  // ncu slot alignment
    gemv_kernel<<<256, 512>>>(x, h, 0, 0, nullptr, 0);

    for (int r = 0; r < NIT; r++) {
        stats_kernel<<<MAXB, 256>>>(b, w);
        fused_kernel<<<17, 256>>>(out, r);
        if (r < NIT - 1)
            gemv_kernel<<<128, 512>>>(nullptr, nullptr, 1, 3 + r, out, r);
        else
            finalG_kernel<<<16, 128>>>(out);
    }
}